// round 15
// baseline (speedup 1.0000x reference)
#include <cuda_runtime.h>
#include <cuda_fp16.h>
#include <math.h>
#include <stdint.h>

// Problem constants
#define Bc   32
#define Lc   1024
#define Dc   512
#define Hc   8
#define DHc  64
#define DFFc 2048
#define NLc  6
#define Ac   21
#define Mrows (Bc*Lc)   // 32768

// 2-term split: A = Ah + (A' - Ah)/64, A' = fl16(64A - 63Ah)
#define SPLIT_S   64.0f
#define SPLIT_SM1 63.0f
#define W_HI      0.984375f   // 63/64
#define W_LO      0.015625f   // 1/64

// ---------------- PTX helpers ----------------
__device__ __forceinline__ uint32_t smem_u32(const void* p) {
    uint32_t a;
    asm("{ .reg .u64 t; cvta.to.shared.u64 t, %1; cvt.u32.u64 %0, t; }" : "=r"(a) : "l"(p));
    return a;
}
__device__ __forceinline__ void ldm_x4(uint32_t* r, uint32_t addr) {
    asm volatile("ldmatrix.sync.aligned.m8n8.x4.shared.b16 {%0,%1,%2,%3}, [%4];"
                 : "=r"(r[0]), "=r"(r[1]), "=r"(r[2]), "=r"(r[3]) : "r"(addr));
}
__device__ __forceinline__ void mma16816(float* d, const uint32_t* a, uint32_t b0, uint32_t b1) {
    asm volatile("mma.sync.aligned.m16n8k16.row.col.f32.f16.f16.f32 "
                 "{%0,%1,%2,%3}, {%4,%5,%6,%7}, {%8,%9}, {%0,%1,%2,%3};"
                 : "+f"(d[0]), "+f"(d[1]), "+f"(d[2]), "+f"(d[3])
                 : "r"(a[0]), "r"(a[1]), "r"(a[2]), "r"(a[3]), "r"(b0), "r"(b1));
}
#define CP_ASYNC16(dst, src) asm volatile("cp.async.cg.shared.global [%0], [%1], 16;" :: "r"(dst), "l"(src))
#define CP_COMMIT()          asm volatile("cp.async.commit_group;" ::: "memory")
#define CP_WAIT1()           asm volatile("cp.async.wait_group 1;" ::: "memory")

// ---------------- scratch ----------------
__device__ float  g_h[(size_t)Mrows * Dc];
__device__ __half g_qkvh[(size_t)Mrows * 3 * Dc];   // fp16 QKV
__device__ __half g_nh[(size_t)Mrows * Dc];         // hi
__device__ __half g_ns[(size_t)Mrows * Dc];         // scaled residual
__device__ __half g_fh[(size_t)Mrows * DFFc];
__device__ __half g_fs[(size_t)Mrows * DFFc];
#define OFF_QKV 0
#define OFF_WO  4718592
#define OFF_W1  6291456
#define OFF_W2  12582912
#define WT_TOT  18874368
__device__ __half g_wth[WT_TOT];
__device__ __half g_wts[WT_TOT];
__device__ float g_bqkv[NLc * 3 * Dc];

// split helper: v -> (hi, scaled)
__device__ __forceinline__ void split2(float v, __half& hi, __half& sc) {
    hi = __float2half_rn(v);
    sc = __float2half_rn(SPLIT_S * v - SPLIT_SM1 * __half2float(hi));
}
// 8 halves (uint4) -> 8 floats
__device__ __forceinline__ void h8_to_f(const uint4& u, float* f) {
    float2 a = __half22float2(*(const __half2*)&u.x);
    float2 b = __half22float2(*(const __half2*)&u.y);
    float2 c = __half22float2(*(const __half2*)&u.z);
    float2 d = __half22float2(*(const __half2*)&u.w);
    f[0] = a.x; f[1] = a.y; f[2] = b.x; f[3] = b.y;
    f[4] = c.x; f[5] = c.y; f[6] = d.x; f[7] = d.y;
}

// ---------------- weight transpose + split ----------------
__device__ __forceinline__ void wconv_tile(const float* __restrict__ W,
                                           __half* __restrict__ Th, __half* __restrict__ Ts,
                                           int K, int N, int bx, int by) {
    __shared__ float t[32][33];
    int k0 = by * 32, n0 = bx * 32;
    int tx = threadIdx.x, ty = threadIdx.y;  // 32 x 8
#pragma unroll
    for (int i = 0; i < 4; i++)
        t[ty + 8 * i][tx] = W[(size_t)(k0 + ty + 8 * i) * N + n0 + tx];
    __syncthreads();
#pragma unroll
    for (int i = 0; i < 4; i++) {
        float v = t[tx][ty + 8 * i];
        __half hh, hs;
        split2(v, hh, hs);
        size_t o = (size_t)(n0 + ty + 8 * i) * K + k0 + tx;
        Th[o] = hh;
        Ts[o] = hs;
    }
}

// z jobs 0..23: layer*4 + {wq,wk,wv,wo}; z job 24: pack fused QKV bias
__global__ void wconv_sq_k(const float* __restrict__ wq, const float* __restrict__ wk,
                           const float* __restrict__ wv, const float* __restrict__ wo,
                           const float* __restrict__ bq, const float* __restrict__ bk,
                           const float* __restrict__ bv, float* __restrict__ bqkv,
                           __half* __restrict__ Th, __half* __restrict__ Ts) {
    int job = blockIdx.z;
    if (job == 24) {
        int bidx = blockIdx.y * 16 + blockIdx.x;
        int i = bidx * 256 + threadIdx.y * 32 + threadIdx.x;
        if (i >= NLc * 3 * Dc) return;
        int l = i / (3 * Dc), c = i % (3 * Dc);
        float v = (c < Dc) ? bq[l * Dc + c]
                : (c < 2 * Dc) ? bk[l * Dc + c - Dc] : bv[l * Dc + c - 2 * Dc];
        bqkv[i] = v;
        return;
    }
    int l = job >> 2, w = job & 3;
    const float* src;
    size_t dst;
    if (w == 0)      { src = wq + (size_t)l * 512 * 512; dst = OFF_QKV + (size_t)l * 1536 * 512; }
    else if (w == 1) { src = wk + (size_t)l * 512 * 512; dst = OFF_QKV + (size_t)l * 1536 * 512 + 512 * 512; }
    else if (w == 2) { src = wv + (size_t)l * 512 * 512; dst = OFF_QKV + (size_t)l * 1536 * 512 + 1024 * 512; }
    else             { src = wo + (size_t)l * 512 * 512; dst = OFF_WO + (size_t)l * 512 * 512; }
    wconv_tile(src, Th + dst, Ts + dst, 512, 512, blockIdx.x, blockIdx.y);
}

__global__ void wconv_rect_k(const float* __restrict__ w1, const float* __restrict__ w2,
                             __half* __restrict__ Th, __half* __restrict__ Ts) {
    int job = blockIdx.z;
    if (job < 6) {
        size_t dst = OFF_W1 + (size_t)job * 2048 * 512;
        wconv_tile(w1 + (size_t)job * 512 * 2048, Th + dst, Ts + dst, 512, 2048,
                   blockIdx.x, blockIdx.y);
    } else {
        int l = job - 6;
        int t = blockIdx.y * 64 + blockIdx.x;
        int bx = t & 15, by = t >> 4;
        size_t dst = OFF_W2 + (size_t)l * 512 * 2048;
        wconv_tile(w2 + (size_t)l * 2048 * 512, Th + dst, Ts + dst, 2048, 512, bx, by);
    }
}

// ---------------- LN core (warp per row) ----------------
__device__ __forceinline__ void ln_row(const float4* v, const float* gs, const float* gb,
                                       __half* Yh, __half* Ys, size_t rowBase, int lane) {
    float s = 0.f;
#pragma unroll
    for (int t = 0; t < 4; t++) s += v[t].x + v[t].y + v[t].z + v[t].w;
#pragma unroll
    for (int o = 16; o; o >>= 1) s += __shfl_xor_sync(0xffffffffu, s, o);
    float mu = s * (1.0f / Dc);
    float ss = 0.f;
#pragma unroll
    for (int t = 0; t < 4; t++) {
        float dx = v[t].x - mu, dy = v[t].y - mu, dz = v[t].z - mu, dw = v[t].w - mu;
        ss += dx * dx + dy * dy + dz * dz + dw * dw;
    }
#pragma unroll
    for (int o = 16; o; o >>= 1) ss += __shfl_xor_sync(0xffffffffu, ss, o);
    float rs = rsqrtf(ss * (1.0f / Dc) + 1e-6f);
#pragma unroll
    for (int t = 0; t < 4; t++) {
        int f4 = lane + 32 * t;
        float4 g4 = ((const float4*)gs)[f4];
        float4 b4 = ((const float4*)gb)[f4];
        float y0 = (v[t].x - mu) * rs * g4.x + b4.x;
        float y1 = (v[t].y - mu) * rs * g4.y + b4.y;
        float y2 = (v[t].z - mu) * rs * g4.z + b4.z;
        float y3 = (v[t].w - mu) * rs * g4.w + b4.w;
        __half h0, s0, h1, s1, h2, s2, h3, s3;
        split2(y0, h0, s0); split2(y1, h1, s1);
        split2(y2, h2, s2); split2(y3, h3, s3);
        __half2 ph0; ph0.x = h0; ph0.y = h1;
        __half2 ph1; ph1.x = h2; ph1.y = h3;
        __half2 ps0; ps0.x = s0; ps0.y = s1;
        __half2 ps1; ps1.x = s2; ps1.y = s3;
        size_t base = rowBase + f4 * 4;
        *(__half2*)(Yh + base) = ph0;
        *(__half2*)(Yh + base + 2) = ph1;
        *(__half2*)(Ys + base) = ps0;
        *(__half2*)(Ys + base + 2) = ps1;
    }
}

__global__ void ln_hf_k(const float* __restrict__ X, const float* __restrict__ gs,
                        const float* __restrict__ gb, __half* __restrict__ Yh,
                        __half* __restrict__ Ys) {
    int w = (int)((blockIdx.x * blockDim.x + threadIdx.x) >> 5);
    int lane = threadIdx.x & 31;
    if (w >= Mrows) return;
    const float* x = X + (size_t)w * Dc;
    float4 v[4];
#pragma unroll
    for (int t = 0; t < 4; t++) v[t] = ((const float4*)x)[lane + 32 * t];
    ln_row(v, gs, gb, Yh, Ys, (size_t)w * Dc, lane);
}

__global__ void embed_ln_k(const int* __restrict__ x, const float* __restrict__ tok,
                           const float* __restrict__ pos, float* __restrict__ h,
                           const float* __restrict__ gs, const float* __restrict__ gb,
                           __half* __restrict__ Yh, __half* __restrict__ Ys) {
    int w = (int)((blockIdx.x * blockDim.x + threadIdx.x) >> 5);
    int lane = threadIdx.x & 31;
    if (w >= Mrows) return;
    int t = x[w];
    int l = w & (Lc - 1);
    float4 v[4];
#pragma unroll
    for (int i = 0; i < 4; i++) {
        float4 a = ((const float4*)tok)[(size_t)t * (Dc / 4) + lane + 32 * i];
        float4 p = ((const float4*)pos)[(size_t)l * (Dc / 4) + lane + 32 * i];
        v[i].x = a.x + p.x; v[i].y = a.y + p.y; v[i].z = a.z + p.z; v[i].w = a.w + p.w;
        ((float4*)(h + (size_t)w * Dc))[lane + 32 * i] = v[i];
    }
    ln_row(v, gs, gb, Yh, Ys, (size_t)w * Dc, lane);
}

// ---------------- fast accurate gelu ----------------
__device__ __forceinline__ float gelu_fast(float x) {
    float v = x * (1.5957691216057308f + 0.07135660900000000f * x * x);
    float e = __expf(v);
    return x - __fdividef(x, e + 1.0f);
}

// ---------------- 2-term split GEMM: 128Mx128N, 8 warps (warp 32x64), 1 CTA/SM --
// C = (63/64)*T1 + U/64 + bias;  EPI 0: fp16 out; EPI 1: gelu+split; EPI 2: fp32+resid
// Stage 64KB: Ah @0 | As @16384 | Bh @32768 | Bs @49152
#define STG_BYTES 65536
#define NSTG 2

template <int EPI>
__global__ void __launch_bounds__(256, 1) gemm_hm(
    const __half* __restrict__ Ah, const __half* __restrict__ As,
    const __half* __restrict__ Bh, const __half* __restrict__ Bs,
    const float* __restrict__ bias, const float* __restrict__ R,
    float* __restrict__ Cf, __half* __restrict__ Ch, __half* __restrict__ Cs,
    int M, int N, int K) {
    extern __shared__ char smraw[];
    uint32_t sb = smem_u32(smraw);
    uint32_t S = (sb + 1023) & ~1023u;

    const int tid = threadIdx.x;
    const int lane = tid & 31;
    const int wid = tid >> 5;
    const int warpM = wid >> 1;   // 0..3 (32 rows each)
    const int warpN = wid & 1;    // 0..1 (64 cols each)

    const size_t mBase = (size_t)blockIdx.y * 128;
    const size_t nBase = (size_t)blockIdx.x * 128;
    const int nch = K >> 6;

    uint32_t aRow[2], bRow[4];
#pragma unroll
    for (int mt = 0; mt < 2; mt++) aRow[mt] = (warpM * 32 + mt * 16 + (lane & 15)) * 128;
#pragma unroll
    for (int g = 0; g < 4; g++) bRow[g] = (warpN * 64 + g * 16 + (lane & 15)) * 128;
    int xor4 = lane >> 4;
    int lsw = lane & 7;
    uint32_t kCh[4];
#pragma unroll
    for (int ks = 0; ks < 4; ks++) kCh[ks] = (uint32_t)(((2 * ks + xor4) ^ lsw) << 4);

    float acc1[2][8][4];   // T1 = Ah*Bh
    float acc2[2][8][4];   // U  = A'*B'
#pragma unroll
    for (int i = 0; i < 2; i++)
#pragma unroll
        for (int j = 0; j < 8; j++)
#pragma unroll
            for (int t = 0; t < 4; t++) { acc1[i][j][t] = 0.f; acc2[i][j][t] = 0.f; }

    // loader: A 128 rows x 8 chunks (1024 jobs), B 128 rows x 8 chunks (1024 jobs)
    auto load_stage = [&](int slot, int ch) {
        uint32_t sdst = S + slot * STG_BYTES;
#pragma unroll
        for (int u = 0; u < 4; u++) {
            int c = tid + u * 256;
            int r = c >> 3, j = c & 7;
            uint32_t d = sdst + r * 128 + (((uint32_t)(j ^ (r & 7))) << 4);
            size_t goA = (mBase + r) * (size_t)K + (size_t)ch * 64 + j * 8;
            CP_ASYNC16(d, Ah + goA);
            CP_ASYNC16(d + 16384, As + goA);
            size_t goB = (nBase + r) * (size_t)K + (size_t)ch * 64 + j * 8;
            CP_ASYNC16(d + 32768, Bh + goB);
            CP_ASYNC16(d + 49152, Bs + goB);
        }
    };

    load_stage(0, 0); CP_COMMIT();
    load_stage(1, 1); CP_COMMIT();

    for (int ch = 0; ch < nch; ch++) {
        CP_WAIT1();
        __syncthreads();
        uint32_t base = S + (ch & 1) * STG_BYTES;
#pragma unroll
        for (int ks = 0; ks < 4; ks++) {
            uint32_t a1f[2][4], a2f[2][4], b1f[4][4], b2f[4][4];
            // batch ALL 12 LDSMs (separate regs; no WAR between terms)
#pragma unroll
            for (int mt = 0; mt < 2; mt++) ldm_x4(a1f[mt], base + aRow[mt] + kCh[ks]);
#pragma unroll
            for (int g = 0; g < 4; g++) ldm_x4(b1f[g], base + 32768 + bRow[g] + kCh[ks]);
#pragma unroll
            for (int mt = 0; mt < 2; mt++) ldm_x4(a2f[mt], base + 16384 + aRow[mt] + kCh[ks]);
#pragma unroll
            for (int g = 0; g < 4; g++) ldm_x4(b2f[g], base + 49152 + bRow[g] + kCh[ks]);
            // 64 back-to-back MMAs
#pragma unroll
            for (int mt = 0; mt < 2; mt++)
#pragma unroll
                for (int nt = 0; nt < 8; nt++)
                    mma16816(acc1[mt][nt], a1f[mt], b1f[nt >> 1][nt & 1], b1f[nt >> 1][(nt & 1) + 2]);
#pragma unroll
            for (int mt = 0; mt < 2; mt++)
#pragma unroll
                for (int nt = 0; nt < 8; nt++)
                    mma16816(acc2[mt][nt], a2f[mt], b2f[nt >> 1][nt & 1], b2f[nt >> 1][(nt & 1) + 2]);
        }
        __syncthreads();
        if (ch + 2 < nch) load_stage(ch & 1, ch + 2);
        CP_COMMIT();
    }

    // epilogue
    int r = lane >> 2;
    int cc = (lane & 3) * 2;
#pragma unroll
    for (int mt = 0; mt < 2; mt++) {
        size_t row0 = mBase + warpM * 32 + mt * 16 + r;
#pragma unroll
        for (int hf = 0; hf < 2; hf++) {
            size_t row = row0 + hf * 8;
#pragma unroll
            for (int nt = 0; nt < 8; nt++) {
                int col = (int)nBase + warpN * 64 + nt * 8 + cc;
                float v0 = W_HI * acc1[mt][nt][hf * 2 + 0] + W_LO * acc2[mt][nt][hf * 2 + 0] + bias[col];
                float v1 = W_HI * acc1[mt][nt][hf * 2 + 1] + W_LO * acc2[mt][nt][hf * 2 + 1] + bias[col + 1];
                size_t o = row * (size_t)N + col;
                if (EPI == 0) {
                    __half2 ph;
                    ph.x = __float2half_rn(v0);
                    ph.y = __float2half_rn(v1);
                    *(__half2*)(Ch + o) = ph;
                } else if (EPI == 1) {
                    v0 = gelu_fast(v0);
                    v1 = gelu_fast(v1);
                    __half h0, s0, h1, s1;
                    split2(v0, h0, s0);
                    split2(v1, h1, s1);
                    __half2 ph; ph.x = h0; ph.y = h1;
                    __half2 ps; ps.x = s0; ps.y = s1;
                    *(__half2*)(Ch + o) = ph;
                    *(__half2*)(Cs + o) = ps;
                } else {
                    float2 rv = *(const float2*)(R + o);
                    v0 += rv.x; v1 += rv.y;
                    float2 ov; ov.x = v0; ov.y = v1;
                    *(float2*)(Cf + o) = ov;
                }
            }
        }
    }
}

// ---------------- junction-tree attention (fp16 QKV): 4 lanes x 8 key-groups ----
__global__ void attn_k(const __half* __restrict__ QKV, __half* __restrict__ Oh,
                       __half* __restrict__ Os) {
    int gw = (int)((blockIdx.x * blockDim.x + threadIdx.x) >> 5);
    int lane = threadIdx.x & 31;
    int g = lane >> 2;
    int q = lane & 3;
    int h = gw & (Hc - 1);
    int bl = gw >> 3;
    int l = bl & (Lc - 1);
    int c = l >> 2, rr = l & 3;
    int ob = c << 2;

    int nk = (c > 0) ? (5 + rr) : (rr + 1);
    int key = (c > 0) ? ((g < 4) ? (ob - 4 + g) : (ob + g - 4)) : (ob + g);
    bool valid = g < nk;

    size_t base3 = (size_t)(bl - l) * (3 * Dc);
    const __half* Qp = QKV + (size_t)bl * (3 * Dc) + h * DHc + q * 16;
    const __half* Kp = QKV + base3 + (size_t)key * (3 * Dc) + Dc + h * DHc + q * 16;
    const __half* Vp = QKV + base3 + (size_t)key * (3 * Dc) + 2 * Dc + h * DHc + q * 16;

    float qv[16];
    {
        uint4 qa = *(const uint4*)Qp;
        uint4 qb = *(const uint4*)(Qp + 8);
        h8_to_f(qa, qv);
        h8_to_f(qb, qv + 8);
    }
    float part = 0.f;
    if (valid) {
        float kv[16];
        uint4 ka = *(const uint4*)Kp;
        uint4 kb = *(const uint4*)(Kp + 8);
        h8_to_f(ka, kv);
        h8_to_f(kb, kv + 8);
#pragma unroll
        for (int t = 0; t < 16; t++) part += qv[t] * kv[t];
    }
    part += __shfl_xor_sync(0xffffffffu, part, 1);
    part += __shfl_xor_sync(0xffffffffu, part, 2);
    float s = valid ? part * 0.125f : -1e30f;

    float mx = s;
    mx = fmaxf(mx, __shfl_xor_sync(0xffffffffu, mx, 4));
    mx = fmaxf(mx, __shfl_xor_sync(0xffffffffu, mx, 8));
    mx = fmaxf(mx, __shfl_xor_sync(0xffffffffu, mx, 16));
    float e = __expf(s - mx);
    float sum = e;
    sum += __shfl_xor_sync(0xffffffffu, sum, 4);
    sum += __shfl_xor_sync(0xffffffffu, sum, 8);
    sum += __shfl_xor_sync(0xffffffffu, sum, 16);
    float p = e / sum;

    float ov[16];
    if (valid) {
        float vv[16];
        uint4 va = *(const uint4*)Vp;
        uint4 vb = *(const uint4*)(Vp + 8);
        h8_to_f(va, vv);
        h8_to_f(vb, vv + 8);
#pragma unroll
        for (int t = 0; t < 16; t++) ov[t] = p * vv[t];
    } else {
#pragma unroll
        for (int t = 0; t < 16; t++) ov[t] = 0.f;
    }
#pragma unroll
    for (int off = 4; off <= 16; off <<= 1) {
#pragma unroll
        for (int t = 0; t < 16; t++) ov[t] += __shfl_xor_sync(0xffffffffu, ov[t], off);
    }
    if (g == 0) {
        size_t oo = (size_t)bl * Dc + h * DHc + q * 16;
#pragma unroll
        for (int t = 0; t < 8; t++) {
            __half h0, s0, h1, s1;
            split2(ov[2 * t], h0, s0);
            split2(ov[2 * t + 1], h1, s1);
            __half2 ph; ph.x = h0; ph.y = h1;
            __half2 ps; ps.x = s0; ps.y = s1;
            *(__half2*)(Oh + oo + 2 * t) = ph;
            *(__half2*)(Os + oo + 2 * t) = ps;
        }
    }
}

// ---------------- final projection ----------------
__global__ void out_k(const float* __restrict__ Hx, const float* __restrict__ Wt,
                      const float* __restrict__ bout, float* __restrict__ out) {
    int w = (int)((blockIdx.x * blockDim.x + threadIdx.x) >> 5);
    int lane = threadIdx.x & 31;
    if (w >= Mrows) return;
    const float* hr = Hx + (size_t)w * Dc;
    float hv[16];
#pragma unroll
    for (int t = 0; t < 16; t++) hv[t] = hr[lane + 32 * t];
    for (int n = 0; n < Ac; n++) {
        float a = 0.f;
#pragma unroll
        for (int t = 0; t < 16; t++) a += hv[t] * Wt[(lane + 32 * t) * Ac + n];
#pragma unroll
        for (int o = 16; o; o >>= 1) a += __shfl_xor_sync(0xffffffffu, a, o);
        if (lane == 0) out[(size_t)w * Ac + n] = a + bout[n];
    }
}

// ---------------- launch ----------------
extern "C" void kernel_launch(void* const* d_in, const int* in_sizes, int n_in,
                              void* d_out, int out_size) {
    const int*   x    = (const int*)d_in[0];
    const float* tok  = (const float*)d_in[2];
    const float* pos  = (const float*)d_in[3];
    const float* wq   = (const float*)d_in[4];
    const float* bq   = (const float*)d_in[5];
    const float* wk   = (const float*)d_in[6];
    const float* bk   = (const float*)d_in[7];
    const float* wv   = (const float*)d_in[8];
    const float* bv   = (const float*)d_in[9];
    const float* wo   = (const float*)d_in[10];
    const float* bo   = (const float*)d_in[11];
    const float* ln1s = (const float*)d_in[12];
    const float* ln1b = (const float*)d_in[13];
    const float* ln2s = (const float*)d_in[14];
    const float* ln2b = (const float*)d_in[15];
    const float* w1   = (const float*)d_in[16];
    const float* b1   = (const float*)d_in[17];
    const float* w2   = (const float*)d_in[18];
    const float* b2   = (const float*)d_in[19];
    const float* wout = (const float*)d_in[20];
    const float* bout = (const float*)d_in[21];
    float* outp = (float*)d_out;

    float *hb, *bqkvb;
    __half *qkvhb, *nh, *ns, *fh, *fs, *wth, *wts;
    cudaGetSymbolAddress((void**)&hb, g_h);
    cudaGetSymbolAddress((void**)&qkvhb, g_qkvh);
    cudaGetSymbolAddress((void**)&bqkvb, g_bqkv);
    cudaGetSymbolAddress((void**)&nh, g_nh);
    cudaGetSymbolAddress((void**)&ns, g_ns);
    cudaGetSymbolAddress((void**)&fh, g_fh);
    cudaGetSymbolAddress((void**)&fs, g_fs);
    cudaGetSymbolAddress((void**)&wth, g_wth);
    cudaGetSymbolAddress((void**)&wts, g_wts);

    const int SMEM = NSTG * STG_BYTES + 1024;  // 132 KB
    static bool attr_done = false;
    if (!attr_done) {
        cudaFuncSetAttribute(gemm_hm<0>, cudaFuncAttributeMaxDynamicSharedMemorySize, SMEM);
        cudaFuncSetAttribute(gemm_hm<1>, cudaFuncAttributeMaxDynamicSharedMemorySize, SMEM);
        cudaFuncSetAttribute(gemm_hm<2>, cudaFuncAttributeMaxDynamicSharedMemorySize, SMEM);
        attr_done = true;
    }
    const int T = 256;
    const int GT = 256;

    {
        dim3 blk(32, 8);
        wconv_sq_k<<<dim3(16, 16, 25), blk>>>(wq, wk, wv, wo, bq, bk, bv, bqkvb, wth, wts); // 1
        wconv_rect_k<<<dim3(64, 16, 12), blk>>>(w1, w2, wth, wts);                          // 2
    }
    embed_ln_k<<<Mrows / 8, T>>>(x, tok, pos, hb, ln1s, ln1b, nh, ns);                      // 3

    dim3 gQKV(1536 / 128, Mrows / 128);  // (12, 256)
    dim3 gD(Dc / 128, Mrows / 128);      // (4, 256)
    dim3 gFF(DFFc / 128, Mrows / 128);   // (16, 256)

    for (int l = 0; l < NLc; l++) {
        size_t qo = OFF_QKV + (size_t)l * 1536 * 512;
        size_t oo = OFF_WO + (size_t)l * 512 * 512;
        size_t o1 = OFF_W1 + (size_t)l * 2048 * 512;
        size_t o2 = OFF_W2 + (size_t)l * 512 * 2048;

        if (l > 0)
            ln_hf_k<<<Mrows / 8, T>>>(hb, ln1s + l * Dc, ln1b + l * Dc, nh, ns);
        gemm_hm<0><<<gQKV, GT, SMEM>>>(nh, ns, wth + qo, wts + qo, bqkvb + l * 1536,
                                       nullptr, nullptr, qkvhb, nullptr, Mrows, 1536, 512); // 4 on l==0 (profiled)
        attn_k<<<(Mrows * Hc) / 8, T>>>(qkvhb, nh, ns);
        gemm_hm<2><<<gD, GT, SMEM>>>(nh, ns, wth + oo, wts + oo, bo + l * Dc,
                                     hb, hb, nullptr, nullptr, Mrows, 512, 512);
        ln_hf_k<<<Mrows / 8, T>>>(hb, ln2s + l * Dc, ln2b + l * Dc, nh, ns);
        gemm_hm<1><<<gFF, GT, SMEM>>>(nh, ns, wth + o1, wts + o1, b1 + l * DFFc,
                                      nullptr, nullptr, fh, fs, Mrows, 2048, 512);
        gemm_hm<2><<<gD, GT, SMEM>>>(fh, fs, wth + o2, wts + o2, b2 + l * Dc,
                                     hb, hb, nullptr, nullptr, Mrows, 512, 2048);
    }

    out_k<<<Mrows / 8, T>>>(hb, wout, bout, outp);
}

// round 16
// speedup vs baseline: 1.0524x; 1.0524x over previous
#include <cuda_runtime.h>
#include <cuda_fp16.h>
#include <math.h>
#include <stdint.h>

// Problem constants
#define Bc   32
#define Lc   1024
#define Dc   512
#define Hc   8
#define DHc  64
#define DFFc 2048
#define NLc  6
#define Ac   21
#define Mrows (Bc*Lc)   // 32768

// 2-term split: A = Ah + (A' - Ah)/64, A' = fl16(64A - 63Ah)
#define SPLIT_S   64.0f
#define SPLIT_SM1 63.0f
#define W_HI      0.984375f   // 63/64
#define W_LO      0.015625f   // 1/64

// ---------------- PTX helpers ----------------
__device__ __forceinline__ uint32_t smem_u32(const void* p) {
    uint32_t a;
    asm("{ .reg .u64 t; cvta.to.shared.u64 t, %1; cvt.u32.u64 %0, t; }" : "=r"(a) : "l"(p));
    return a;
}
__device__ __forceinline__ void ldm_x4(uint32_t* r, uint32_t addr) {
    asm volatile("ldmatrix.sync.aligned.m8n8.x4.shared.b16 {%0,%1,%2,%3}, [%4];"
                 : "=r"(r[0]), "=r"(r[1]), "=r"(r[2]), "=r"(r[3]) : "r"(addr));
}
__device__ __forceinline__ void mma16816(float* d, const uint32_t* a, uint32_t b0, uint32_t b1) {
    asm volatile("mma.sync.aligned.m16n8k16.row.col.f32.f16.f16.f32 "
                 "{%0,%1,%2,%3}, {%4,%5,%6,%7}, {%8,%9}, {%0,%1,%2,%3};"
                 : "+f"(d[0]), "+f"(d[1]), "+f"(d[2]), "+f"(d[3])
                 : "r"(a[0]), "r"(a[1]), "r"(a[2]), "r"(a[3]), "r"(b0), "r"(b1));
}
#define CP_ASYNC16(dst, src) asm volatile("cp.async.cg.shared.global [%0], [%1], 16;" :: "r"(dst), "l"(src))
#define CP_COMMIT()          asm volatile("cp.async.commit_group;" ::: "memory")
#define CP_WAIT1()           asm volatile("cp.async.wait_group 1;" ::: "memory")

// ---------------- scratch ----------------
__device__ float  g_h[(size_t)Mrows * Dc];
__device__ __half g_qkvh[(size_t)Mrows * 3 * Dc];   // fp16 QKV
__device__ __half g_nh[(size_t)Mrows * Dc];         // hi
__device__ __half g_ns[(size_t)Mrows * Dc];         // scaled residual
__device__ __half g_fh[(size_t)Mrows * DFFc];
__device__ __half g_fs[(size_t)Mrows * DFFc];
#define OFF_QKV 0
#define OFF_WO  4718592
#define OFF_W1  6291456
#define OFF_W2  12582912
#define WT_TOT  18874368
__device__ __half g_wth[WT_TOT];
__device__ __half g_wts[WT_TOT];
__device__ float g_bqkv[NLc * 3 * Dc];

// split helper: v -> (hi, scaled)
__device__ __forceinline__ void split2(float v, __half& hi, __half& sc) {
    hi = __float2half_rn(v);
    sc = __float2half_rn(SPLIT_S * v - SPLIT_SM1 * __half2float(hi));
}
// 8 halves (uint4) -> 8 floats
__device__ __forceinline__ void h8_to_f(const uint4& u, float* f) {
    float2 a = __half22float2(*(const __half2*)&u.x);
    float2 b = __half22float2(*(const __half2*)&u.y);
    float2 c = __half22float2(*(const __half2*)&u.z);
    float2 d = __half22float2(*(const __half2*)&u.w);
    f[0] = a.x; f[1] = a.y; f[2] = b.x; f[3] = b.y;
    f[4] = c.x; f[5] = c.y; f[6] = d.x; f[7] = d.y;
}

// ---------------- weight transpose + split ----------------
__device__ __forceinline__ void wconv_tile(const float* __restrict__ W,
                                           __half* __restrict__ Th, __half* __restrict__ Ts,
                                           int K, int N, int bx, int by) {
    __shared__ float t[32][33];
    int k0 = by * 32, n0 = bx * 32;
    int tx = threadIdx.x, ty = threadIdx.y;  // 32 x 8
#pragma unroll
    for (int i = 0; i < 4; i++)
        t[ty + 8 * i][tx] = W[(size_t)(k0 + ty + 8 * i) * N + n0 + tx];
    __syncthreads();
#pragma unroll
    for (int i = 0; i < 4; i++) {
        float v = t[tx][ty + 8 * i];
        __half hh, hs;
        split2(v, hh, hs);
        size_t o = (size_t)(n0 + ty + 8 * i) * K + k0 + tx;
        Th[o] = hh;
        Ts[o] = hs;
    }
}

// z jobs 0..23: layer*4 + {wq,wk,wv,wo}; z job 24: pack fused QKV bias
__global__ void wconv_sq_k(const float* __restrict__ wq, const float* __restrict__ wk,
                           const float* __restrict__ wv, const float* __restrict__ wo,
                           const float* __restrict__ bq, const float* __restrict__ bk,
                           const float* __restrict__ bv, float* __restrict__ bqkv,
                           __half* __restrict__ Th, __half* __restrict__ Ts) {
    int job = blockIdx.z;
    if (job == 24) {
        int bidx = blockIdx.y * 16 + blockIdx.x;
        int i = bidx * 256 + threadIdx.y * 32 + threadIdx.x;
        if (i >= NLc * 3 * Dc) return;
        int l = i / (3 * Dc), c = i % (3 * Dc);
        float v = (c < Dc) ? bq[l * Dc + c]
                : (c < 2 * Dc) ? bk[l * Dc + c - Dc] : bv[l * Dc + c - 2 * Dc];
        bqkv[i] = v;
        return;
    }
    int l = job >> 2, w = job & 3;
    const float* src;
    size_t dst;
    if (w == 0)      { src = wq + (size_t)l * 512 * 512; dst = OFF_QKV + (size_t)l * 1536 * 512; }
    else if (w == 1) { src = wk + (size_t)l * 512 * 512; dst = OFF_QKV + (size_t)l * 1536 * 512 + 512 * 512; }
    else if (w == 2) { src = wv + (size_t)l * 512 * 512; dst = OFF_QKV + (size_t)l * 1536 * 512 + 1024 * 512; }
    else             { src = wo + (size_t)l * 512 * 512; dst = OFF_WO + (size_t)l * 512 * 512; }
    wconv_tile(src, Th + dst, Ts + dst, 512, 512, blockIdx.x, blockIdx.y);
}

__global__ void wconv_rect_k(const float* __restrict__ w1, const float* __restrict__ w2,
                             __half* __restrict__ Th, __half* __restrict__ Ts) {
    int job = blockIdx.z;
    if (job < 6) {
        size_t dst = OFF_W1 + (size_t)job * 2048 * 512;
        wconv_tile(w1 + (size_t)job * 512 * 2048, Th + dst, Ts + dst, 512, 2048,
                   blockIdx.x, blockIdx.y);
    } else {
        int l = job - 6;
        int t = blockIdx.y * 64 + blockIdx.x;
        int bx = t & 15, by = t >> 4;
        size_t dst = OFF_W2 + (size_t)l * 512 * 2048;
        wconv_tile(w2 + (size_t)l * 2048 * 512, Th + dst, Ts + dst, 2048, 512, bx, by);
    }
}

// ---------------- LN core (warp per row) ----------------
__device__ __forceinline__ void ln_row(const float4* v, const float* gs, const float* gb,
                                       __half* Yh, __half* Ys, size_t rowBase, int lane) {
    float s = 0.f;
#pragma unroll
    for (int t = 0; t < 4; t++) s += v[t].x + v[t].y + v[t].z + v[t].w;
#pragma unroll
    for (int o = 16; o; o >>= 1) s += __shfl_xor_sync(0xffffffffu, s, o);
    float mu = s * (1.0f / Dc);
    float ss = 0.f;
#pragma unroll
    for (int t = 0; t < 4; t++) {
        float dx = v[t].x - mu, dy = v[t].y - mu, dz = v[t].z - mu, dw = v[t].w - mu;
        ss += dx * dx + dy * dy + dz * dz + dw * dw;
    }
#pragma unroll
    for (int o = 16; o; o >>= 1) ss += __shfl_xor_sync(0xffffffffu, ss, o);
    float rs = rsqrtf(ss * (1.0f / Dc) + 1e-6f);
#pragma unroll
    for (int t = 0; t < 4; t++) {
        int f4 = lane + 32 * t;
        float4 g4 = ((const float4*)gs)[f4];
        float4 b4 = ((const float4*)gb)[f4];
        float y0 = (v[t].x - mu) * rs * g4.x + b4.x;
        float y1 = (v[t].y - mu) * rs * g4.y + b4.y;
        float y2 = (v[t].z - mu) * rs * g4.z + b4.z;
        float y3 = (v[t].w - mu) * rs * g4.w + b4.w;
        __half h0, s0, h1, s1, h2, s2, h3, s3;
        split2(y0, h0, s0); split2(y1, h1, s1);
        split2(y2, h2, s2); split2(y3, h3, s3);
        __half2 ph0; ph0.x = h0; ph0.y = h1;
        __half2 ph1; ph1.x = h2; ph1.y = h3;
        __half2 ps0; ps0.x = s0; ps0.y = s1;
        __half2 ps1; ps1.x = s2; ps1.y = s3;
        size_t base = rowBase + f4 * 4;
        *(__half2*)(Yh + base) = ph0;
        *(__half2*)(Yh + base + 2) = ph1;
        *(__half2*)(Ys + base) = ps0;
        *(__half2*)(Ys + base + 2) = ps1;
    }
}

__global__ void ln_hf_k(const float* __restrict__ X, const float* __restrict__ gs,
                        const float* __restrict__ gb, __half* __restrict__ Yh,
                        __half* __restrict__ Ys) {
    int w = (int)((blockIdx.x * blockDim.x + threadIdx.x) >> 5);
    int lane = threadIdx.x & 31;
    if (w >= Mrows) return;
    const float* x = X + (size_t)w * Dc;
    float4 v[4];
#pragma unroll
    for (int t = 0; t < 4; t++) v[t] = ((const float4*)x)[lane + 32 * t];
    ln_row(v, gs, gb, Yh, Ys, (size_t)w * Dc, lane);
}

__global__ void embed_ln_k(const int* __restrict__ x, const float* __restrict__ tok,
                           const float* __restrict__ pos, float* __restrict__ h,
                           const float* __restrict__ gs, const float* __restrict__ gb,
                           __half* __restrict__ Yh, __half* __restrict__ Ys) {
    int w = (int)((blockIdx.x * blockDim.x + threadIdx.x) >> 5);
    int lane = threadIdx.x & 31;
    if (w >= Mrows) return;
    int t = x[w];
    int l = w & (Lc - 1);
    float4 v[4];
#pragma unroll
    for (int i = 0; i < 4; i++) {
        float4 a = ((const float4*)tok)[(size_t)t * (Dc / 4) + lane + 32 * i];
        float4 p = ((const float4*)pos)[(size_t)l * (Dc / 4) + lane + 32 * i];
        v[i].x = a.x + p.x; v[i].y = a.y + p.y; v[i].z = a.z + p.z; v[i].w = a.w + p.w;
        ((float4*)(h + (size_t)w * Dc))[lane + 32 * i] = v[i];
    }
    ln_row(v, gs, gb, Yh, Ys, (size_t)w * Dc, lane);
}

// ---------------- fast accurate gelu ----------------
__device__ __forceinline__ float gelu_fast(float x) {
    float v = x * (1.5957691216057308f + 0.07135660900000000f * x * x);
    float e = __expf(v);
    return x - __fdividef(x, e + 1.0f);
}

// ---------------- 2-term split GEMM: 128Mx64N, 8 warps (warp 32x32), 2 CTAs/SM --
// (round-13 proven configuration)
#define STG_BYTES 49152   // Ah 16K | As 16K | Bh 8K | Bs 8K
#define NSTG 2

template <int EPI>
__global__ void __launch_bounds__(256, 2) gemm_hm(
    const __half* __restrict__ Ah, const __half* __restrict__ As,
    const __half* __restrict__ Bh, const __half* __restrict__ Bs,
    const float* __restrict__ bias, const float* __restrict__ R,
    float* __restrict__ Cf, __half* __restrict__ Ch, __half* __restrict__ Cs,
    int M, int N, int K) {
    extern __shared__ char smraw[];
    uint32_t sb = smem_u32(smraw);
    uint32_t S = (sb + 1023) & ~1023u;

    const int tid = threadIdx.x;
    const int lane = tid & 31;
    const int wid = tid >> 5;
    const int warpM = wid >> 1;   // 0..3
    const int warpN = wid & 1;    // 0..1

    const size_t mBase = (size_t)blockIdx.y * 128;
    const size_t nBase = (size_t)blockIdx.x * 64;
    const int nch = K >> 6;

    uint32_t aRow[2], bRow[2];
#pragma unroll
    for (int mt = 0; mt < 2; mt++) aRow[mt] = (warpM * 32 + mt * 16 + (lane & 15)) * 128;
#pragma unroll
    for (int g = 0; g < 2; g++) bRow[g] = (warpN * 32 + g * 16 + (lane & 15)) * 128;
    int xor4 = lane >> 4;
    int lsw = lane & 7;
    uint32_t kCh[4];
#pragma unroll
    for (int ks = 0; ks < 4; ks++) kCh[ks] = (uint32_t)(((2 * ks + xor4) ^ lsw) << 4);

    float acc1[2][4][4];   // T1 = Ah*Bh
    float acc2[2][4][4];   // U  = A'*B'
#pragma unroll
    for (int i = 0; i < 2; i++)
#pragma unroll
        for (int j = 0; j < 4; j++)
#pragma unroll
            for (int t = 0; t < 4; t++) { acc1[i][j][t] = 0.f; acc2[i][j][t] = 0.f; }

    // stage: Ah @0 (16K), As @16384, Bh @32768 (8K), Bs @40960
    auto load_stage = [&](int slot, int ch) {
        uint32_t sdst = S + slot * STG_BYTES;
#pragma unroll
        for (int u = 0; u < 4; u++) {
            int c = tid + u * 256;            // A: 128 rows x 8 chunks
            int r = c >> 3, j = c & 7;
            size_t go = (mBase + r) * (size_t)K + (size_t)ch * 64 + j * 8;
            uint32_t d = sdst + r * 128 + (((uint32_t)(j ^ (r & 7))) << 4);
            CP_ASYNC16(d, Ah + go);
            CP_ASYNC16(d + 16384, As + go);
        }
#pragma unroll
        for (int u = 0; u < 2; u++) {
            int c = tid + u * 256;            // B: 64 rows x 8 chunks
            int r = c >> 3, j = c & 7;
            size_t go = (nBase + r) * (size_t)K + (size_t)ch * 64 + j * 8;
            uint32_t d = sdst + 32768 + r * 128 + (((uint32_t)(j ^ (r & 7))) << 4);
            CP_ASYNC16(d, Bh + go);
            CP_ASYNC16(d + 8192, Bs + go);
        }
    };

    load_stage(0, 0); CP_COMMIT();
    load_stage(1, 1); CP_COMMIT();

    for (int ch = 0; ch < nch; ch++) {
        CP_WAIT1();
        __syncthreads();
        uint32_t base = S + (ch & 1) * STG_BYTES;
#pragma unroll
        for (int ks = 0; ks < 4; ks++) {
            uint32_t a1f[2][4], b1f[2][4], a2f[2][4], b2f[2][4];
            // batch ALL loads (separate regs: no WAR between terms)
#pragma unroll
            for (int mt = 0; mt < 2; mt++) ldm_x4(a1f[mt], base + aRow[mt] + kCh[ks]);
#pragma unroll
            for (int g = 0; g < 2; g++) ldm_x4(b1f[g], base + 32768 + bRow[g] + kCh[ks]);
#pragma unroll
            for (int mt = 0; mt < 2; mt++) ldm_x4(a2f[mt], base + 16384 + aRow[mt] + kCh[ks]);
#pragma unroll
            for (int g = 0; g < 2; g++) ldm_x4(b2f[g], base + 40960 + bRow[g] + kCh[ks]);
            // 32 back-to-back MMAs
#pragma unroll
            for (int mt = 0; mt < 2; mt++)
#pragma unroll
                for (int nt = 0; nt < 4; nt++)
                    mma16816(acc1[mt][nt], a1f[mt], b1f[nt >> 1][nt & 1], b1f[nt >> 1][(nt & 1) + 2]);
#pragma unroll
            for (int mt = 0; mt < 2; mt++)
#pragma unroll
                for (int nt = 0; nt < 4; nt++)
                    mma16816(acc2[mt][nt], a2f[mt], b2f[nt >> 1][nt & 1], b2f[nt >> 1][(nt & 1) + 2]);
        }
        __syncthreads();
        if (ch + 2 < nch) load_stage(ch & 1, ch + 2);
        CP_COMMIT();
    }

    // epilogue
    int r = lane >> 2;
    int cc = (lane & 3) * 2;
#pragma unroll
    for (int mt = 0; mt < 2; mt++) {
        size_t row0 = mBase + warpM * 32 + mt * 16 + r;
#pragma unroll
        for (int hf = 0; hf < 2; hf++) {
            size_t row = row0 + hf * 8;
#pragma unroll
            for (int nt = 0; nt < 4; nt++) {
                int col = (int)nBase + warpN * 32 + nt * 8 + cc;
                float v0 = W_HI * acc1[mt][nt][hf * 2 + 0] + W_LO * acc2[mt][nt][hf * 2 + 0] + bias[col];
                float v1 = W_HI * acc1[mt][nt][hf * 2 + 1] + W_LO * acc2[mt][nt][hf * 2 + 1] + bias[col + 1];
                size_t o = row * (size_t)N + col;
                if (EPI == 0) {
                    __half2 ph;
                    ph.x = __float2half_rn(v0);
                    ph.y = __float2half_rn(v1);
                    *(__half2*)(Ch + o) = ph;
                } else if (EPI == 1) {
                    v0 = gelu_fast(v0);
                    v1 = gelu_fast(v1);
                    __half h0, s0, h1, s1;
                    split2(v0, h0, s0);
                    split2(v1, h1, s1);
                    __half2 ph; ph.x = h0; ph.y = h1;
                    __half2 ps; ps.x = s0; ps.y = s1;
                    *(__half2*)(Ch + o) = ph;
                    *(__half2*)(Cs + o) = ps;
                } else {
                    float2 rv = *(const float2*)(R + o);
                    v0 += rv.x; v1 += rv.y;
                    float2 ov; ov.x = v0; ov.y = v1;
                    *(float2*)(Cf + o) = ov;
                }
            }
        }
    }
}

// ---------------- junction-tree attention (fp16 QKV): 4 lanes x 8 key-groups ----
__global__ void attn_k(const __half* __restrict__ QKV, __half* __restrict__ Oh,
                       __half* __restrict__ Os) {
    int gw = (int)((blockIdx.x * blockDim.x + threadIdx.x) >> 5);
    int lane = threadIdx.x & 31;
    int g = lane >> 2;
    int q = lane & 3;
    int h = gw & (Hc - 1);
    int bl = gw >> 3;
    int l = bl & (Lc - 1);
    int c = l >> 2, rr = l & 3;
    int ob = c << 2;

    int nk = (c > 0) ? (5 + rr) : (rr + 1);
    int key = (c > 0) ? ((g < 4) ? (ob - 4 + g) : (ob + g - 4)) : (ob + g);
    bool valid = g < nk;

    size_t base3 = (size_t)(bl - l) * (3 * Dc);
    const __half* Qp = QKV + (size_t)bl * (3 * Dc) + h * DHc + q * 16;
    const __half* Kp = QKV + base3 + (size_t)key * (3 * Dc) + Dc + h * DHc + q * 16;
    const __half* Vp = QKV + base3 + (size_t)key * (3 * Dc) + 2 * Dc + h * DHc + q * 16;

    float qv[16];
    {
        uint4 qa = *(const uint4*)Qp;
        uint4 qb = *(const uint4*)(Qp + 8);
        h8_to_f(qa, qv);
        h8_to_f(qb, qv + 8);
    }
    float part = 0.f;
    if (valid) {
        float kv[16];
        uint4 ka = *(const uint4*)Kp;
        uint4 kb = *(const uint4*)(Kp + 8);
        h8_to_f(ka, kv);
        h8_to_f(kb, kv + 8);
#pragma unroll
        for (int t = 0; t < 16; t++) part += qv[t] * kv[t];
    }
    part += __shfl_xor_sync(0xffffffffu, part, 1);
    part += __shfl_xor_sync(0xffffffffu, part, 2);
    float s = valid ? part * 0.125f : -1e30f;

    float mx = s;
    mx = fmaxf(mx, __shfl_xor_sync(0xffffffffu, mx, 4));
    mx = fmaxf(mx, __shfl_xor_sync(0xffffffffu, mx, 8));
    mx = fmaxf(mx, __shfl_xor_sync(0xffffffffu, mx, 16));
    float e = __expf(s - mx);
    float sum = e;
    sum += __shfl_xor_sync(0xffffffffu, sum, 4);
    sum += __shfl_xor_sync(0xffffffffu, sum, 8);
    sum += __shfl_xor_sync(0xffffffffu, sum, 16);
    float p = e / sum;

    float ov[16];
    if (valid) {
        float vv[16];
        uint4 va = *(const uint4*)Vp;
        uint4 vb = *(const uint4*)(Vp + 8);
        h8_to_f(va, vv);
        h8_to_f(vb, vv + 8);
#pragma unroll
        for (int t = 0; t < 16; t++) ov[t] = p * vv[t];
    } else {
#pragma unroll
        for (int t = 0; t < 16; t++) ov[t] = 0.f;
    }
#pragma unroll
    for (int off = 4; off <= 16; off <<= 1) {
#pragma unroll
        for (int t = 0; t < 16; t++) ov[t] += __shfl_xor_sync(0xffffffffu, ov[t], off);
    }
    if (g == 0) {
        size_t oo = (size_t)bl * Dc + h * DHc + q * 16;
#pragma unroll
        for (int t = 0; t < 8; t++) {
            __half h0, s0, h1, s1;
            split2(ov[2 * t], h0, s0);
            split2(ov[2 * t + 1], h1, s1);
            __half2 ph; ph.x = h0; ph.y = h1;
            __half2 ps; ps.x = s0; ps.y = s1;
            *(__half2*)(Oh + oo + 2 * t) = ph;
            *(__half2*)(Os + oo + 2 * t) = ps;
        }
    }
}

// ---------------- final projection: wout staged in smem ----------------
__global__ void __launch_bounds__(256) out_k(const float* __restrict__ Hx,
                                             const float* __restrict__ Wt,
                                             const float* __restrict__ bout,
                                             float* __restrict__ out) {
    __shared__ float swt[Dc * Ac];   // 512*21 fp32 = 43008 B
    __shared__ float sbo[Ac];
    int tid = threadIdx.x;
    for (int i = tid; i < Dc * Ac; i += 256) swt[i] = Wt[i];
    if (tid < Ac) sbo[tid] = bout[tid];
    __syncthreads();

    int w = blockIdx.x * 8 + (tid >> 5);
    int lane = tid & 31;
    if (w >= Mrows) return;
    const float* hr = Hx + (size_t)w * Dc;
    float hv[16];
#pragma unroll
    for (int t = 0; t < 16; t++) hv[t] = hr[lane + 32 * t];
    for (int n = 0; n < Ac; n++) {
        float a = 0.f;
#pragma unroll
        for (int t = 0; t < 16; t++) a += hv[t] * swt[(lane + 32 * t) * Ac + n];
#pragma unroll
        for (int o = 16; o; o >>= 1) a += __shfl_xor_sync(0xffffffffu, a, o);
        if (lane == 0) out[(size_t)w * Ac + n] = a + sbo[n];
    }
}

// ---------------- launch ----------------
extern "C" void kernel_launch(void* const* d_in, const int* in_sizes, int n_in,
                              void* d_out, int out_size) {
    const int*   x    = (const int*)d_in[0];
    const float* tok  = (const float*)d_in[2];
    const float* pos  = (const float*)d_in[3];
    const float* wq   = (const float*)d_in[4];
    const float* bq   = (const float*)d_in[5];
    const float* wk   = (const float*)d_in[6];
    const float* bk   = (const float*)d_in[7];
    const float* wv   = (const float*)d_in[8];
    const float* bv   = (const float*)d_in[9];
    const float* wo   = (const float*)d_in[10];
    const float* bo   = (const float*)d_in[11];
    const float* ln1s = (const float*)d_in[12];
    const float* ln1b = (const float*)d_in[13];
    const float* ln2s = (const float*)d_in[14];
    const float* ln2b = (const float*)d_in[15];
    const float* w1   = (const float*)d_in[16];
    const float* b1   = (const float*)d_in[17];
    const float* w2   = (const float*)d_in[18];
    const float* b2   = (const float*)d_in[19];
    const float* wout = (const float*)d_in[20];
    const float* bout = (const float*)d_in[21];
    float* outp = (float*)d_out;

    float *hb, *bqkvb;
    __half *qkvhb, *nh, *ns, *fh, *fs, *wth, *wts;
    cudaGetSymbolAddress((void**)&hb, g_h);
    cudaGetSymbolAddress((void**)&qkvhb, g_qkvh);
    cudaGetSymbolAddress((void**)&bqkvb, g_bqkv);
    cudaGetSymbolAddress((void**)&nh, g_nh);
    cudaGetSymbolAddress((void**)&ns, g_ns);
    cudaGetSymbolAddress((void**)&fh, g_fh);
    cudaGetSymbolAddress((void**)&fs, g_fs);
    cudaGetSymbolAddress((void**)&wth, g_wth);
    cudaGetSymbolAddress((void**)&wts, g_wts);

    const int SMEM = NSTG * STG_BYTES + 1024;
    static bool attr_done = false;
    if (!attr_done) {
        cudaFuncSetAttribute(gemm_hm<0>, cudaFuncAttributeMaxDynamicSharedMemorySize, SMEM);
        cudaFuncSetAttribute(gemm_hm<1>, cudaFuncAttributeMaxDynamicSharedMemorySize, SMEM);
        cudaFuncSetAttribute(gemm_hm<2>, cudaFuncAttributeMaxDynamicSharedMemorySize, SMEM);
        attr_done = true;
    }
    const int T = 256;
    const int GT = 256;

    {
        dim3 blk(32, 8);
        wconv_sq_k<<<dim3(16, 16, 25), blk>>>(wq, wk, wv, wo, bq, bk, bv, bqkvb, wth, wts); // 1
        wconv_rect_k<<<dim3(64, 16, 12), blk>>>(w1, w2, wth, wts);                          // 2
    }
    embed_ln_k<<<Mrows / 8, T>>>(x, tok, pos, hb, ln1s, ln1b, nh, ns);                      // 3

    dim3 gQKV(1536 / 64, Mrows / 128);  // (24, 256)
    dim3 gD(Dc / 64, Mrows / 128);      // (8, 256)
    dim3 gFF(DFFc / 64, Mrows / 128);   // (32, 256)

    for (int l = 0; l < NLc; l++) {
        size_t qo = OFF_QKV + (size_t)l * 1536 * 512;
        size_t oo = OFF_WO + (size_t)l * 512 * 512;
        size_t o1 = OFF_W1 + (size_t)l * 2048 * 512;
        size_t o2 = OFF_W2 + (size_t)l * 512 * 2048;

        if (l > 0)
            ln_hf_k<<<Mrows / 8, T>>>(hb, ln1s + l * Dc, ln1b + l * Dc, nh, ns);
        gemm_hm<0><<<gQKV, GT, SMEM>>>(nh, ns, wth + qo, wts + qo, bqkvb + l * 1536,
                                       nullptr, nullptr, qkvhb, nullptr, Mrows, 1536, 512); // 4 on l==0 (profiled)
        attn_k<<<(Mrows * Hc) / 8, T>>>(qkvhb, nh, ns);
        gemm_hm<2><<<gD, GT, SMEM>>>(nh, ns, wth + oo, wts + oo, bo + l * Dc,
                                     hb, hb, nullptr, nullptr, Mrows, 512, 512);
        ln_hf_k<<<Mrows / 8, T>>>(hb, ln2s + l * Dc, ln2b + l * Dc, nh, ns);
        gemm_hm<1><<<gFF, GT, SMEM>>>(nh, ns, wth + o1, wts + o1, b1 + l * DFFc,
                                      nullptr, nullptr, fh, fs, Mrows, 2048, 512);
        gemm_hm<2><<<gD, GT, SMEM>>>(fh, fs, wth + o2, wts + o2, b2 + l * Dc,
                                     hb, hb, nullptr, nullptr, Mrows, 512, 2048);
    }

    out_k<<<Mrows / 8, T>>>(hb, wout, bout, outp);
}

// round 17
// speedup vs baseline: 1.0588x; 1.0061x over previous
#include <cuda_runtime.h>
#include <cuda_fp16.h>
#include <math.h>
#include <stdint.h>

// Problem constants
#define Bc   32
#define Lc   1024
#define Dc   512
#define Hc   8
#define DHc  64
#define DFFc 2048
#define NLc  6
#define Ac   21
#define Mrows (Bc*Lc)   // 32768

// 2-term split: A = Ah + (A' - Ah)/64, A' = fl16(64A - 63Ah)
#define SPLIT_S   64.0f
#define SPLIT_SM1 63.0f
#define W_HI      0.984375f   // 63/64
#define W_LO      0.015625f   // 1/64

// ---------------- PTX helpers ----------------
__device__ __forceinline__ uint32_t smem_u32(const void* p) {
    uint32_t a;
    asm("{ .reg .u64 t; cvta.to.shared.u64 t, %1; cvt.u32.u64 %0, t; }" : "=r"(a) : "l"(p));
    return a;
}
__device__ __forceinline__ void ldm_x4(uint32_t* r, uint32_t addr) {
    asm volatile("ldmatrix.sync.aligned.m8n8.x4.shared.b16 {%0,%1,%2,%3}, [%4];"
                 : "=r"(r[0]), "=r"(r[1]), "=r"(r[2]), "=r"(r[3]) : "r"(addr));
}
__device__ __forceinline__ void mma16816(float* d, const uint32_t* a, uint32_t b0, uint32_t b1) {
    asm volatile("mma.sync.aligned.m16n8k16.row.col.f32.f16.f16.f32 "
                 "{%0,%1,%2,%3}, {%4,%5,%6,%7}, {%8,%9}, {%0,%1,%2,%3};"
                 : "+f"(d[0]), "+f"(d[1]), "+f"(d[2]), "+f"(d[3])
                 : "r"(a[0]), "r"(a[1]), "r"(a[2]), "r"(a[3]), "r"(b0), "r"(b1));
}
#define CP_ASYNC16(dst, src) asm volatile("cp.async.cg.shared.global [%0], [%1], 16;" :: "r"(dst), "l"(src))
#define CP_COMMIT()          asm volatile("cp.async.commit_group;" ::: "memory")
#define CP_WAIT1()           asm volatile("cp.async.wait_group 1;" ::: "memory")

// ---------------- scratch ----------------
__device__ float  g_h[(size_t)Mrows * Dc];
__device__ __half g_qkvh[(size_t)Mrows * 3 * Dc];   // fp16 QKV
__device__ __half g_nh[(size_t)Mrows * Dc];         // hi
__device__ __half g_ns[(size_t)Mrows * Dc];         // scaled residual
__device__ __half g_fh[(size_t)Mrows * DFFc];
__device__ __half g_fs[(size_t)Mrows * DFFc];
#define OFF_QKV 0
#define OFF_WO  4718592
#define OFF_W1  6291456
#define OFF_W2  12582912
#define WT_TOT  18874368
__device__ __half g_wth[WT_TOT];
__device__ __half g_wts[WT_TOT];
__device__ float g_bqkv[NLc * 3 * Dc];

// split helper: v -> (hi, scaled)
__device__ __forceinline__ void split2(float v, __half& hi, __half& sc) {
    hi = __float2half_rn(v);
    sc = __float2half_rn(SPLIT_S * v - SPLIT_SM1 * __half2float(hi));
}
// 8 halves (uint4) -> 8 floats
__device__ __forceinline__ void h8_to_f(const uint4& u, float* f) {
    float2 a = __half22float2(*(const __half2*)&u.x);
    float2 b = __half22float2(*(const __half2*)&u.y);
    float2 c = __half22float2(*(const __half2*)&u.z);
    float2 d = __half22float2(*(const __half2*)&u.w);
    f[0] = a.x; f[1] = a.y; f[2] = b.x; f[3] = b.y;
    f[4] = c.x; f[5] = c.y; f[6] = d.x; f[7] = d.y;
}

// ---------------- weight transpose + split ----------------
__device__ __forceinline__ void wconv_tile(const float* __restrict__ W,
                                           __half* __restrict__ Th, __half* __restrict__ Ts,
                                           int K, int N, int bx, int by) {
    __shared__ float t[32][33];
    int k0 = by * 32, n0 = bx * 32;
    int tx = threadIdx.x, ty = threadIdx.y;  // 32 x 8
#pragma unroll
    for (int i = 0; i < 4; i++)
        t[ty + 8 * i][tx] = W[(size_t)(k0 + ty + 8 * i) * N + n0 + tx];
    __syncthreads();
#pragma unroll
    for (int i = 0; i < 4; i++) {
        float v = t[tx][ty + 8 * i];
        __half hh, hs;
        split2(v, hh, hs);
        size_t o = (size_t)(n0 + ty + 8 * i) * K + k0 + tx;
        Th[o] = hh;
        Ts[o] = hs;
    }
}

// z jobs 0..23: layer*4 + {wq,wk,wv,wo}; z job 24: pack fused QKV bias
__global__ void wconv_sq_k(const float* __restrict__ wq, const float* __restrict__ wk,
                           const float* __restrict__ wv, const float* __restrict__ wo,
                           const float* __restrict__ bq, const float* __restrict__ bk,
                           const float* __restrict__ bv, float* __restrict__ bqkv,
                           __half* __restrict__ Th, __half* __restrict__ Ts) {
    int job = blockIdx.z;
    if (job == 24) {
        int bidx = blockIdx.y * 16 + blockIdx.x;
        int i = bidx * 256 + threadIdx.y * 32 + threadIdx.x;
        if (i >= NLc * 3 * Dc) return;
        int l = i / (3 * Dc), c = i % (3 * Dc);
        float v = (c < Dc) ? bq[l * Dc + c]
                : (c < 2 * Dc) ? bk[l * Dc + c - Dc] : bv[l * Dc + c - 2 * Dc];
        bqkv[i] = v;
        return;
    }
    int l = job >> 2, w = job & 3;
    const float* src;
    size_t dst;
    if (w == 0)      { src = wq + (size_t)l * 512 * 512; dst = OFF_QKV + (size_t)l * 1536 * 512; }
    else if (w == 1) { src = wk + (size_t)l * 512 * 512; dst = OFF_QKV + (size_t)l * 1536 * 512 + 512 * 512; }
    else if (w == 2) { src = wv + (size_t)l * 512 * 512; dst = OFF_QKV + (size_t)l * 1536 * 512 + 1024 * 512; }
    else             { src = wo + (size_t)l * 512 * 512; dst = OFF_WO + (size_t)l * 512 * 512; }
    wconv_tile(src, Th + dst, Ts + dst, 512, 512, blockIdx.x, blockIdx.y);
}

__global__ void wconv_rect_k(const float* __restrict__ w1, const float* __restrict__ w2,
                             __half* __restrict__ Th, __half* __restrict__ Ts) {
    int job = blockIdx.z;
    if (job < 6) {
        size_t dst = OFF_W1 + (size_t)job * 2048 * 512;
        wconv_tile(w1 + (size_t)job * 512 * 2048, Th + dst, Ts + dst, 512, 2048,
                   blockIdx.x, blockIdx.y);
    } else {
        int l = job - 6;
        int t = blockIdx.y * 64 + blockIdx.x;
        int bx = t & 15, by = t >> 4;
        size_t dst = OFF_W2 + (size_t)l * 512 * 2048;
        wconv_tile(w2 + (size_t)l * 2048 * 512, Th + dst, Ts + dst, 2048, 512, bx, by);
    }
}

// ---------------- LN core (warp per row) ----------------
__device__ __forceinline__ void ln_row(const float4* v, const float* gs, const float* gb,
                                       __half* Yh, __half* Ys, size_t rowBase, int lane) {
    float s = 0.f;
#pragma unroll
    for (int t = 0; t < 4; t++) s += v[t].x + v[t].y + v[t].z + v[t].w;
#pragma unroll
    for (int o = 16; o; o >>= 1) s += __shfl_xor_sync(0xffffffffu, s, o);
    float mu = s * (1.0f / Dc);
    float ss = 0.f;
#pragma unroll
    for (int t = 0; t < 4; t++) {
        float dx = v[t].x - mu, dy = v[t].y - mu, dz = v[t].z - mu, dw = v[t].w - mu;
        ss += dx * dx + dy * dy + dz * dz + dw * dw;
    }
#pragma unroll
    for (int o = 16; o; o >>= 1) ss += __shfl_xor_sync(0xffffffffu, ss, o);
    float rs = rsqrtf(ss * (1.0f / Dc) + 1e-6f);
#pragma unroll
    for (int t = 0; t < 4; t++) {
        int f4 = lane + 32 * t;
        float4 g4 = ((const float4*)gs)[f4];
        float4 b4 = ((const float4*)gb)[f4];
        float y0 = (v[t].x - mu) * rs * g4.x + b4.x;
        float y1 = (v[t].y - mu) * rs * g4.y + b4.y;
        float y2 = (v[t].z - mu) * rs * g4.z + b4.z;
        float y3 = (v[t].w - mu) * rs * g4.w + b4.w;
        __half h0, s0, h1, s1, h2, s2, h3, s3;
        split2(y0, h0, s0); split2(y1, h1, s1);
        split2(y2, h2, s2); split2(y3, h3, s3);
        __half2 ph0; ph0.x = h0; ph0.y = h1;
        __half2 ph1; ph1.x = h2; ph1.y = h3;
        __half2 ps0; ps0.x = s0; ps0.y = s1;
        __half2 ps1; ps1.x = s2; ps1.y = s3;
        size_t base = rowBase + f4 * 4;
        *(__half2*)(Yh + base) = ph0;
        *(__half2*)(Yh + base + 2) = ph1;
        *(__half2*)(Ys + base) = ps0;
        *(__half2*)(Ys + base + 2) = ps1;
    }
}

__global__ void ln_hf_k(const float* __restrict__ X, const float* __restrict__ gs,
                        const float* __restrict__ gb, __half* __restrict__ Yh,
                        __half* __restrict__ Ys) {
    int w = (int)((blockIdx.x * blockDim.x + threadIdx.x) >> 5);
    int lane = threadIdx.x & 31;
    if (w >= Mrows) return;
    const float* x = X + (size_t)w * Dc;
    float4 v[4];
#pragma unroll
    for (int t = 0; t < 4; t++) v[t] = ((const float4*)x)[lane + 32 * t];
    ln_row(v, gs, gb, Yh, Ys, (size_t)w * Dc, lane);
}

__global__ void embed_ln_k(const int* __restrict__ x, const float* __restrict__ tok,
                           const float* __restrict__ pos, float* __restrict__ h,
                           const float* __restrict__ gs, const float* __restrict__ gb,
                           __half* __restrict__ Yh, __half* __restrict__ Ys) {
    int w = (int)((blockIdx.x * blockDim.x + threadIdx.x) >> 5);
    int lane = threadIdx.x & 31;
    if (w >= Mrows) return;
    int t = x[w];
    int l = w & (Lc - 1);
    float4 v[4];
#pragma unroll
    for (int i = 0; i < 4; i++) {
        float4 a = ((const float4*)tok)[(size_t)t * (Dc / 4) + lane + 32 * i];
        float4 p = ((const float4*)pos)[(size_t)l * (Dc / 4) + lane + 32 * i];
        v[i].x = a.x + p.x; v[i].y = a.y + p.y; v[i].z = a.z + p.z; v[i].w = a.w + p.w;
        ((float4*)(h + (size_t)w * Dc))[lane + 32 * i] = v[i];
    }
    ln_row(v, gs, gb, Yh, Ys, (size_t)w * Dc, lane);
}

// ---------------- fast accurate gelu ----------------
__device__ __forceinline__ float gelu_fast(float x) {
    float v = x * (1.5957691216057308f + 0.07135660900000000f * x * x);
    float e = __expf(v);
    return x - __fdividef(x, e + 1.0f);
}

// ---------------- 2-term split GEMM: 128Mx64N, 8 warps (warp 32x32), 2 CTAs/SM --
// (round-13/16 proven configuration — unchanged)
#define STG_BYTES 49152   // Ah 16K | As 16K | Bh 8K | Bs 8K
#define NSTG 2

template <int EPI>
__global__ void __launch_bounds__(256, 2) gemm_hm(
    const __half* __restrict__ Ah, const __half* __restrict__ As,
    const __half* __restrict__ Bh, const __half* __restrict__ Bs,
    const float* __restrict__ bias, const float* __restrict__ R,
    float* __restrict__ Cf, __half* __restrict__ Ch, __half* __restrict__ Cs,
    int M, int N, int K) {
    extern __shared__ char smraw[];
    uint32_t sb = smem_u32(smraw);
    uint32_t S = (sb + 1023) & ~1023u;

    const int tid = threadIdx.x;
    const int lane = tid & 31;
    const int wid = tid >> 5;
    const int warpM = wid >> 1;   // 0..3
    const int warpN = wid & 1;    // 0..1

    const size_t mBase = (size_t)blockIdx.y * 128;
    const size_t nBase = (size_t)blockIdx.x * 64;
    const int nch = K >> 6;

    uint32_t aRow[2], bRow[2];
#pragma unroll
    for (int mt = 0; mt < 2; mt++) aRow[mt] = (warpM * 32 + mt * 16 + (lane & 15)) * 128;
#pragma unroll
    for (int g = 0; g < 2; g++) bRow[g] = (warpN * 32 + g * 16 + (lane & 15)) * 128;
    int xor4 = lane >> 4;
    int lsw = lane & 7;
    uint32_t kCh[4];
#pragma unroll
    for (int ks = 0; ks < 4; ks++) kCh[ks] = (uint32_t)(((2 * ks + xor4) ^ lsw) << 4);

    float acc1[2][4][4];   // T1 = Ah*Bh
    float acc2[2][4][4];   // U  = A'*B'
#pragma unroll
    for (int i = 0; i < 2; i++)
#pragma unroll
        for (int j = 0; j < 4; j++)
#pragma unroll
            for (int t = 0; t < 4; t++) { acc1[i][j][t] = 0.f; acc2[i][j][t] = 0.f; }

    // stage: Ah @0 (16K), As @16384, Bh @32768 (8K), Bs @40960
    auto load_stage = [&](int slot, int ch) {
        uint32_t sdst = S + slot * STG_BYTES;
#pragma unroll
        for (int u = 0; u < 4; u++) {
            int c = tid + u * 256;            // A: 128 rows x 8 chunks
            int r = c >> 3, j = c & 7;
            size_t go = (mBase + r) * (size_t)K + (size_t)ch * 64 + j * 8;
            uint32_t d = sdst + r * 128 + (((uint32_t)(j ^ (r & 7))) << 4);
            CP_ASYNC16(d, Ah + go);
            CP_ASYNC16(d + 16384, As + go);
        }
#pragma unroll
        for (int u = 0; u < 2; u++) {
            int c = tid + u * 256;            // B: 64 rows x 8 chunks
            int r = c >> 3, j = c & 7;
            size_t go = (nBase + r) * (size_t)K + (size_t)ch * 64 + j * 8;
            uint32_t d = sdst + 32768 + r * 128 + (((uint32_t)(j ^ (r & 7))) << 4);
            CP_ASYNC16(d, Bh + go);
            CP_ASYNC16(d + 8192, Bs + go);
        }
    };

    load_stage(0, 0); CP_COMMIT();
    load_stage(1, 1); CP_COMMIT();

    for (int ch = 0; ch < nch; ch++) {
        CP_WAIT1();
        __syncthreads();
        uint32_t base = S + (ch & 1) * STG_BYTES;
#pragma unroll
        for (int ks = 0; ks < 4; ks++) {
            uint32_t a1f[2][4], b1f[2][4], a2f[2][4], b2f[2][4];
#pragma unroll
            for (int mt = 0; mt < 2; mt++) ldm_x4(a1f[mt], base + aRow[mt] + kCh[ks]);
#pragma unroll
            for (int g = 0; g < 2; g++) ldm_x4(b1f[g], base + 32768 + bRow[g] + kCh[ks]);
#pragma unroll
            for (int mt = 0; mt < 2; mt++) ldm_x4(a2f[mt], base + 16384 + aRow[mt] + kCh[ks]);
#pragma unroll
            for (int g = 0; g < 2; g++) ldm_x4(b2f[g], base + 40960 + bRow[g] + kCh[ks]);
#pragma unroll
            for (int mt = 0; mt < 2; mt++)
#pragma unroll
                for (int nt = 0; nt < 4; nt++)
                    mma16816(acc1[mt][nt], a1f[mt], b1f[nt >> 1][nt & 1], b1f[nt >> 1][(nt & 1) + 2]);
#pragma unroll
            for (int mt = 0; mt < 2; mt++)
#pragma unroll
                for (int nt = 0; nt < 4; nt++)
                    mma16816(acc2[mt][nt], a2f[mt], b2f[nt >> 1][nt & 1], b2f[nt >> 1][(nt & 1) + 2]);
        }
        __syncthreads();
        if (ch + 2 < nch) load_stage(ch & 1, ch + 2);
        CP_COMMIT();
    }

    // epilogue
    int r = lane >> 2;
    int cc = (lane & 3) * 2;
#pragma unroll
    for (int mt = 0; mt < 2; mt++) {
        size_t row0 = mBase + warpM * 32 + mt * 16 + r;
#pragma unroll
        for (int hf = 0; hf < 2; hf++) {
            size_t row = row0 + hf * 8;
#pragma unroll
            for (int nt = 0; nt < 4; nt++) {
                int col = (int)nBase + warpN * 32 + nt * 8 + cc;
                float v0 = W_HI * acc1[mt][nt][hf * 2 + 0] + W_LO * acc2[mt][nt][hf * 2 + 0] + bias[col];
                float v1 = W_HI * acc1[mt][nt][hf * 2 + 1] + W_LO * acc2[mt][nt][hf * 2 + 1] + bias[col + 1];
                size_t o = row * (size_t)N + col;
                if (EPI == 0) {
                    __half2 ph;
                    ph.x = __float2half_rn(v0);
                    ph.y = __float2half_rn(v1);
                    *(__half2*)(Ch + o) = ph;
                } else if (EPI == 1) {
                    v0 = gelu_fast(v0);
                    v1 = gelu_fast(v1);
                    __half h0, s0, h1, s1;
                    split2(v0, h0, s0);
                    split2(v1, h1, s1);
                    __half2 ph; ph.x = h0; ph.y = h1;
                    __half2 ps; ps.x = s0; ps.y = s1;
                    *(__half2*)(Ch + o) = ph;
                    *(__half2*)(Cs + o) = ps;
                } else {
                    float2 rv = *(const float2*)(R + o);
                    v0 += rv.x; v1 += rv.y;
                    float2 ov; ov.x = v0; ov.y = v1;
                    *(float2*)(Cf + o) = ov;
                }
            }
        }
    }
}

// ---------------- clique-shared attention: block per (batch, clique) ----------
// Stages 4 Q rows + 8 K rows + 8 V rows in smem once; 8 warps x 4 (query,head)
// pairs each via the 4-lane x 8-key-group shuffle scheme. K/V rows padded to
// 520 halves (1040B stride => groups hit different banks).
#define KVPAD 520
__global__ void __launch_bounds__(256) attn_k(const __half* __restrict__ QKV,
                                              __half* __restrict__ Oh,
                                              __half* __restrict__ Os) {
    __shared__ __half sQ[4 * 512];
    __shared__ __half sK[8 * KVPAD];
    __shared__ __half sV[8 * KVPAD];

    int b = blockIdx.x >> 8;          // batch
    int c = blockIdx.x & 255;         // clique 0..255
    int tid = threadIdx.x;
    int rowQ0 = b * Lc + c * 4;
    int rowK0 = rowQ0 - 4;            // parent rows (c>0)

    // load Q: 4 rows x 64 u4-chunks = 256 jobs
    {
        int r = tid >> 6, cc = tid & 63;
        const __half* src = QKV + (size_t)(rowQ0 + r) * (3 * Dc) + cc * 8;
        *(uint4*)(sQ + r * 512 + cc * 8) = *(const uint4*)src;
    }
    // load K,V: 8 rows x 64 chunks = 512 jobs (2 per thread)
#pragma unroll
    for (int u = 0; u < 2; u++) {
        int j = tid + u * 256;
        int r = j >> 6, cc = j & 63;
        int gr = (c > 0) ? (rowK0 + r) : (rowQ0 + (r & 3));   // c==0: dup own rows
        const __half* kp = QKV + (size_t)gr * (3 * Dc) + Dc + cc * 8;
        const __half* vp = QKV + (size_t)gr * (3 * Dc) + 2 * Dc + cc * 8;
        *(uint4*)(sK + r * KVPAD + cc * 8) = *(const uint4*)kp;
        *(uint4*)(sV + r * KVPAD + cc * 8) = *(const uint4*)vp;
    }
    __syncthreads();

    int wid = tid >> 5, lane = tid & 31;
    int g = lane >> 2;      // key slot 0..7 (0-3 parent, 4-7 own; c==0: 0-3 own)
    int q4 = lane & 3;      // 16-dim quarter

#pragma unroll
    for (int i = 0; i < 4; i++) {
        int p = wid * 4 + i;
        int qi = p >> 3;    // query-in-clique 0..3
        int h = p & 7;      // head
        int nk = (c > 0) ? (5 + qi) : (qi + 1);
        bool valid = g < nk;

        const __half* qp = sQ + qi * 512 + h * DHc + q4 * 16;
        const __half* kp = sK + g * KVPAD + h * DHc + q4 * 16;
        float qv[16], kv[16];
        h8_to_f(*(const uint4*)qp, qv);
        h8_to_f(*(const uint4*)(qp + 8), qv + 8);
        h8_to_f(*(const uint4*)kp, kv);
        h8_to_f(*(const uint4*)(kp + 8), kv + 8);
        float part = 0.f;
#pragma unroll
        for (int t = 0; t < 16; t++) part += qv[t] * kv[t];
        part += __shfl_xor_sync(0xffffffffu, part, 1);
        part += __shfl_xor_sync(0xffffffffu, part, 2);
        float s = valid ? part * 0.125f : -1e30f;

        float mx = s;
        mx = fmaxf(mx, __shfl_xor_sync(0xffffffffu, mx, 4));
        mx = fmaxf(mx, __shfl_xor_sync(0xffffffffu, mx, 8));
        mx = fmaxf(mx, __shfl_xor_sync(0xffffffffu, mx, 16));
        float e = __expf(s - mx);
        float sum = e;
        sum += __shfl_xor_sync(0xffffffffu, sum, 4);
        sum += __shfl_xor_sync(0xffffffffu, sum, 8);
        sum += __shfl_xor_sync(0xffffffffu, sum, 16);
        float pw = e / sum;

        const __half* vp = sV + g * KVPAD + h * DHc + q4 * 16;
        float ov[16];
        if (valid) {
            float vv[16];
            h8_to_f(*(const uint4*)vp, vv);
            h8_to_f(*(const uint4*)(vp + 8), vv + 8);
#pragma unroll
            for (int t = 0; t < 16; t++) ov[t] = pw * vv[t];
        } else {
#pragma unroll
            for (int t = 0; t < 16; t++) ov[t] = 0.f;
        }
#pragma unroll
        for (int off = 4; off <= 16; off <<= 1) {
#pragma unroll
            for (int t = 0; t < 16; t++) ov[t] += __shfl_xor_sync(0xffffffffu, ov[t], off);
        }
        if (g == 0) {
            size_t oo = (size_t)(rowQ0 + qi) * Dc + h * DHc + q4 * 16;
#pragma unroll
            for (int t = 0; t < 8; t++) {
                __half h0, s0, h1, s1;
                split2(ov[2 * t], h0, s0);
                split2(ov[2 * t + 1], h1, s1);
                __half2 ph; ph.x = h0; ph.y = h1;
                __half2 ps; ps.x = s0; ps.y = s1;
                *(__half2*)(Oh + oo + 2 * t) = ph;
                *(__half2*)(Os + oo + 2 * t) = ps;
            }
        }
    }
}

// ---------------- final projection: wout staged in smem ----------------
__global__ void __launch_bounds__(256) out_k(const float* __restrict__ Hx,
                                             const float* __restrict__ Wt,
                                             const float* __restrict__ bout,
                                             float* __restrict__ out) {
    __shared__ float swt[Dc * Ac];   // 512*21 fp32 = 43008 B
    __shared__ float sbo[Ac];
    int tid = threadIdx.x;
    for (int i = tid; i < Dc * Ac; i += 256) swt[i] = Wt[i];
    if (tid < Ac) sbo[tid] = bout[tid];
    __syncthreads();

    int w = blockIdx.x * 8 + (tid >> 5);
    int lane = tid & 31;
    if (w >= Mrows) return;
    const float* hr = Hx + (size_t)w * Dc;
    float hv[16];
#pragma unroll
    for (int t = 0; t < 16; t++) hv[t] = hr[lane + 32 * t];
    for (int n = 0; n < Ac; n++) {
        float a = 0.f;
#pragma unroll
        for (int t = 0; t < 16; t++) a += hv[t] * swt[(lane + 32 * t) * Ac + n];
#pragma unroll
        for (int o = 16; o; o >>= 1) a += __shfl_xor_sync(0xffffffffu, a, o);
        if (lane == 0) out[(size_t)w * Ac + n] = a + sbo[n];
    }
}

// ---------------- launch ----------------
extern "C" void kernel_launch(void* const* d_in, const int* in_sizes, int n_in,
                              void* d_out, int out_size) {
    const int*   x    = (const int*)d_in[0];
    const float* tok  = (const float*)d_in[2];
    const float* pos  = (const float*)d_in[3];
    const float* wq   = (const float*)d_in[4];
    const float* bq   = (const float*)d_in[5];
    const float* wk   = (const float*)d_in[6];
    const float* bk   = (const float*)d_in[7];
    const float* wv   = (const float*)d_in[8];
    const float* bv   = (const float*)d_in[9];
    const float* wo   = (const float*)d_in[10];
    const float* bo   = (const float*)d_in[11];
    const float* ln1s = (const float*)d_in[12];
    const float* ln1b = (const float*)d_in[13];
    const float* ln2s = (const float*)d_in[14];
    const float* ln2b = (const float*)d_in[15];
    const float* w1   = (const float*)d_in[16];
    const float* b1   = (const float*)d_in[17];
    const float* w2   = (const float*)d_in[18];
    const float* b2   = (const float*)d_in[19];
    const float* wout = (const float*)d_in[20];
    const float* bout = (const float*)d_in[21];
    float* outp = (float*)d_out;

    float *hb, *bqkvb;
    __half *qkvhb, *nh, *ns, *fh, *fs, *wth, *wts;
    cudaGetSymbolAddress((void**)&hb, g_h);
    cudaGetSymbolAddress((void**)&qkvhb, g_qkvh);
    cudaGetSymbolAddress((void**)&bqkvb, g_bqkv);
    cudaGetSymbolAddress((void**)&nh, g_nh);
    cudaGetSymbolAddress((void**)&ns, g_ns);
    cudaGetSymbolAddress((void**)&fh, g_fh);
    cudaGetSymbolAddress((void**)&fs, g_fs);
    cudaGetSymbolAddress((void**)&wth, g_wth);
    cudaGetSymbolAddress((void**)&wts, g_wts);

    const int SMEM = NSTG * STG_BYTES + 1024;
    static bool attr_done = false;
    if (!attr_done) {
        cudaFuncSetAttribute(gemm_hm<0>, cudaFuncAttributeMaxDynamicSharedMemorySize, SMEM);
        cudaFuncSetAttribute(gemm_hm<1>, cudaFuncAttributeMaxDynamicSharedMemorySize, SMEM);
        cudaFuncSetAttribute(gemm_hm<2>, cudaFuncAttributeMaxDynamicSharedMemorySize, SMEM);
        attr_done = true;
    }
    const int T = 256;
    const int GT = 256;

    {
        dim3 blk(32, 8);
        wconv_sq_k<<<dim3(16, 16, 25), blk>>>(wq, wk, wv, wo, bq, bk, bv, bqkvb, wth, wts); // 1
        wconv_rect_k<<<dim3(64, 16, 12), blk>>>(w1, w2, wth, wts);                          // 2
    }
    embed_ln_k<<<Mrows / 8, T>>>(x, tok, pos, hb, ln1s, ln1b, nh, ns);                      // 3

    dim3 gQKV(1536 / 64, Mrows / 128);  // (24, 256)
    dim3 gD(Dc / 64, Mrows / 128);      // (8, 256)
    dim3 gFF(DFFc / 64, Mrows / 128);   // (32, 256)

    for (int l = 0; l < NLc; l++) {
        size_t qo = OFF_QKV + (size_t)l * 1536 * 512;
        size_t oo = OFF_WO + (size_t)l * 512 * 512;
        size_t o1 = OFF_W1 + (size_t)l * 2048 * 512;
        size_t o2 = OFF_W2 + (size_t)l * 512 * 2048;

        if (l > 0)
            ln_hf_k<<<Mrows / 8, T>>>(hb, ln1s + l * Dc, ln1b + l * Dc, nh, ns);
        gemm_hm<0><<<gQKV, GT, SMEM>>>(nh, ns, wth + qo, wts + qo, bqkvb + l * 1536,
                                       nullptr, nullptr, qkvhb, nullptr, Mrows, 1536, 512); // 4 on l==0 (profiled)
        attn_k<<<Bc * (Lc / 4), T>>>(qkvhb, nh, ns);
        gemm_hm<2><<<gD, GT, SMEM>>>(nh, ns, wth + oo, wts + oo, bo + l * Dc,
                                     hb, hb, nullptr, nullptr, Mrows, 512, 512);
        ln_hf_k<<<Mrows / 8, T>>>(hb, ln2s + l * Dc, ln2b + l * Dc, nh, ns);
        gemm_hm<1><<<gFF, GT, SMEM>>>(nh, ns, wth + o1, wts + o1, b1 + l * DFFc,
                                      nullptr, nullptr, fh, fs, Mrows, 2048, 512);
        gemm_hm<2><<<gD, GT, SMEM>>>(fh, fs, wth + o2, wts + o2, b2 + l * Dc,
                                     hb, hb, nullptr, nullptr, Mrows, 512, 2048);
    }

    out_k<<<Mrows / 8, T>>>(hb, wout, bout, outp);
}